// round 16
// baseline (speedup 1.0000x reference)
#include <cuda_runtime.h>
#include <cuda_fp16.h>
#include <cstdint>

#define MAXN 50048
#define MAXW 64                                // ELL width (deg ~ Poisson(16))

// ---------------- scratch (__device__ globals; no allocs allowed) ----------
__device__ int    g_cnt[MAXN];                 // in-degree counter / final degree
__device__ int    g_adj[(size_t)MAXN * MAXW];  // ELL adjacency: src ids (row 256B-aligned)
__device__ __half g_h1[(size_t)MAXN * 128];    // dinv * (X @ W1)       (fp16, pre-scaled)
__device__ __half g_o1[(size_t)MAXN * 128];    // relu(layer-1 out)     (fp16)
__device__ __half g_h2[(size_t)MAXN * 64];     // dinv * (relu(o1)@W2)  (fp16, pre-scaled)

__device__ __forceinline__ float4 h4tof4(uint2 raw) {
    float2 a = __half22float2(*(__half2*)&raw.x);
    float2 b = __half22float2(*(__half2*)&raw.y);
    return make_float4(a.x, a.y, b.x, b.y);
}

// ---------------------------------------------------------------------------
// fill: single pass builds ELL adjacency AND degree counts
// ---------------------------------------------------------------------------
__global__ void k_fill(const int* __restrict__ ei, int* __restrict__ cnt,
                       int* __restrict__ adj, int E) {
    int e = blockIdx.x * blockDim.x + threadIdx.x;
    if (e >= E) return;
    int src = ei[e];
    int dst = ei[E + e];
    int pos = atomicAdd(&cnt[dst], 1);
    if (pos < MAXW) adj[(size_t)dst * MAXW + pos] = src;
}

// ---------------------------------------------------------------------------
// shared fp16 HMMA body (m16n8k16, fp32 accumulate — numerically identical
// to the former tf32 path since inputs carry the same fp16 rounding).
// Xs: [BM][136] halves (m-major).  Wt: [C][136] halves (n-major / k-contig).
// Fragment loads are packed __half2 (LDS.32), bank-conflict-free:
// bank = (4*group + tig) mod 32 covers all 32 lanes distinctly.
// ---------------------------------------------------------------------------
template <int C>
__device__ __forceinline__ void mma_body_epilogue(
    const __half* Xs, const __half* Wt, const int* __restrict__ cnt,
    __half* __restrict__ H, int N, int row0, int wid, int lane) {
    constexpr int K = 128;
    constexpr int XSS_H = 136, KSS_H = 136;
    constexpr int NTILES = C / 16;

    int m0 = (wid & 3) * 16;
    int nbase = (wid >> 2) * (C / 2);
    int g = lane >> 2;          // groupID (row / B-col)
    int t = lane & 3;           // thread-in-group

    float acc[NTILES][4];
#pragma unroll
    for (int tt = 0; tt < NTILES; tt++) {
        acc[tt][0] = 0.f; acc[tt][1] = 0.f; acc[tt][2] = 0.f; acc[tt][3] = 0.f;
    }
#pragma unroll
    for (int k0 = 0; k0 < K; k0 += 16) {
        uint32_t a0 = *(const uint32_t*)(Xs + (m0 + g) * XSS_H + k0 + 2 * t);
        uint32_t a1 = *(const uint32_t*)(Xs + (m0 + g + 8) * XSS_H + k0 + 2 * t);
        uint32_t a2 = *(const uint32_t*)(Xs + (m0 + g) * XSS_H + k0 + 2 * t + 8);
        uint32_t a3 = *(const uint32_t*)(Xs + (m0 + g + 8) * XSS_H + k0 + 2 * t + 8);
#pragma unroll
        for (int tt = 0; tt < NTILES; tt++) {
            int n0 = nbase + tt * 8;
            uint32_t b0 = *(const uint32_t*)(Wt + (n0 + g) * KSS_H + k0 + 2 * t);
            uint32_t b1 = *(const uint32_t*)(Wt + (n0 + g) * KSS_H + k0 + 2 * t + 8);
            asm volatile(
                "mma.sync.aligned.m16n8k16.row.col.f32.f16.f16.f32 "
                "{%0,%1,%2,%3}, {%4,%5,%6,%7}, {%8,%9}, {%0,%1,%2,%3};"
                : "+f"(acc[tt][0]), "+f"(acc[tt][1]), "+f"(acc[tt][2]), "+f"(acc[tt][3])
                : "r"(a0), "r"(a1), "r"(a2), "r"(a3), "r"(b0), "r"(b1));
        }
    }

    int gr0 = row0 + m0 + g;
    int gr1 = gr0 + 8;
    float d0 = (gr0 < N) ? rsqrtf((float)cnt[gr0] + 1.0f) : 0.f;
    float d1 = (gr1 < N) ? rsqrtf((float)cnt[gr1] + 1.0f) : 0.f;
#pragma unroll
    for (int tt = 0; tt < NTILES; tt++) {
        int col = nbase + tt * 8 + 2 * t;
        if (gr0 < N)
            *(__half2*)(H + (size_t)gr0 * C + col) =
                __floats2half2_rn(d0 * acc[tt][0], d0 * acc[tt][1]);
        if (gr1 < N)
            *(__half2*)(H + (size_t)gr1 * C + col) =
                __floats2half2_rn(d1 * acc[tt][2], d1 * acc[tt][3]);
    }
}

// ---------------------------------------------------------------------------
// mma1: X(fp32) @ W1[128,128] -> prescaled fp16 h1.
// ---------------------------------------------------------------------------
__global__ void k_mma1(const float* __restrict__ X, const float* __restrict__ W,
                       const int* __restrict__ cnt, __half* __restrict__ H, int N) {
    constexpr int C = 128, K = 128, BM = 64;
    constexpr int XSS_H = 136, KSS_H = 136;
    extern __shared__ __half smh[];
    __half* Xs = smh;                       // BM * XSS_H
    __half* Wt = smh + BM * XSS_H;          // C * KSS_H  (transposed: [n][k])

    int tid = threadIdx.x;
    int wid = tid >> 5, lane = tid & 31;
    int row0 = blockIdx.x * BM;

#pragma unroll
    for (int it = 0; it < (BM * K) / (256 * 4); it++) {
        int i4 = tid + it * 256;
        int m = i4 >> 5;
        int k = (i4 << 2) & 127;
        int gr = row0 + m;
        if (gr >= N) gr = N - 1;
        float4 v = *(const float4*)(X + (size_t)gr * K + k);
        uint2 st;
        *(__half2*)&st.x = __floats2half2_rn(v.x, v.y);
        *(__half2*)&st.y = __floats2half2_rn(v.z, v.w);
        *(uint2*)(Xs + m * XSS_H + k) = st;
    }
    // stage W transposed: read W[k][n..n+3], write Wt[n..n+3][k]
#pragma unroll
    for (int it = 0; it < (K * C) / (256 * 4); it++) {
        int i4 = tid + it * 256;
        int k = (i4 * 4) / C;
        int n = (i4 * 4) % C;
        float4 v = *(const float4*)(W + (size_t)k * C + n);
        Wt[(n + 0) * KSS_H + k] = __float2half_rn(v.x);
        Wt[(n + 1) * KSS_H + k] = __float2half_rn(v.y);
        Wt[(n + 2) * KSS_H + k] = __float2half_rn(v.z);
        Wt[(n + 3) * KSS_H + k] = __float2half_rn(v.w);
    }
    __syncthreads();

    mma_body_epilogue<C>(Xs, Wt, cnt, H, N, row0, wid, lane);
}

// ---------------------------------------------------------------------------
// mma2: o1(fp16, relu'd) @ W2[128,64] -> prescaled fp16 h2.
// ---------------------------------------------------------------------------
__global__ void k_mma2(const __half* __restrict__ X, const float* __restrict__ W,
                       const int* __restrict__ cnt, __half* __restrict__ H, int N) {
    constexpr int C = 64, K = 128, BM = 64;
    constexpr int XSS_H = 136, KSS_H = 136;
    extern __shared__ __half smh[];
    __half* Xs = smh;
    __half* Wt = smh + BM * XSS_H;

    int tid = threadIdx.x;
    int wid = tid >> 5, lane = tid & 31;
    int row0 = blockIdx.x * BM;

#pragma unroll
    for (int it = 0; it < (BM * K) / (256 * 4); it++) {
        int i4 = tid + it * 256;
        int m = i4 >> 5;
        int k = (i4 << 2) & 127;
        int gr = row0 + m;
        if (gr >= N) gr = N - 1;
        uint2 hv = *(const uint2*)(X + (size_t)gr * K + k);   // already fp16
        *(uint2*)(Xs + m * XSS_H + k) = hv;
    }
#pragma unroll
    for (int it = 0; it < (K * C) / (256 * 4); it++) {
        int i4 = tid + it * 256;
        int k = (i4 * 4) / C;
        int n = (i4 * 4) % C;
        float4 v = *(const float4*)(W + (size_t)k * C + n);
        Wt[(n + 0) * KSS_H + k] = __float2half_rn(v.x);
        Wt[(n + 1) * KSS_H + k] = __float2half_rn(v.y);
        Wt[(n + 2) * KSS_H + k] = __float2half_rn(v.z);
        Wt[(n + 3) * KSS_H + k] = __float2half_rn(v.w);
    }
    __syncthreads();

    mma_body_epilogue<C>(Xs, Wt, cnt, H, N, row0, wid, lane);
}

// ---------------------------------------------------------------------------
// agg128: warp per dst row; fp16 output with fused relu.
// o1[row] = relu(dinv_d * (Sum hs[s] + hs[row]) + bias)   (fp16)
// ---------------------------------------------------------------------------
__global__ void k_agg128(const __half* __restrict__ H, const int* __restrict__ cnt,
                         const float* __restrict__ bias, const int* __restrict__ adj,
                         __half* __restrict__ O, int N) {
    int row  = blockIdx.x * (blockDim.x >> 5) + (threadIdx.x >> 5);
    int lane = threadIdx.x & 31;
    if (row >= N) return;
    int c0 = lane * 4;
    int deg_e = cnt[row];
    int nedge = deg_e < MAXW ? deg_e : MAXW;
    float dinv_d = rsqrtf((float)deg_e + 1.0f);

    const int4* ab4 = (const int4*)(adj + (size_t)row * MAXW);
    float4 es = h4tof4(*(const uint2*)(H + (size_t)row * 128 + c0));
    int j = 0;
    for (; j + 7 < nedge; j += 8) {
        int4 q0 = ab4[j >> 2];
        int4 q1 = ab4[(j >> 2) + 1];
        uint2 r0 = *(const uint2*)(H + (size_t)q0.x * 128 + c0);
        uint2 r1 = *(const uint2*)(H + (size_t)q0.y * 128 + c0);
        uint2 r2 = *(const uint2*)(H + (size_t)q0.z * 128 + c0);
        uint2 r3 = *(const uint2*)(H + (size_t)q0.w * 128 + c0);
        uint2 r4 = *(const uint2*)(H + (size_t)q1.x * 128 + c0);
        uint2 r5 = *(const uint2*)(H + (size_t)q1.y * 128 + c0);
        uint2 r6 = *(const uint2*)(H + (size_t)q1.z * 128 + c0);
        uint2 r7 = *(const uint2*)(H + (size_t)q1.w * 128 + c0);
        __half2 pa0 = __hadd2(*(__half2*)&r0.x, *(__half2*)&r1.x);
        __half2 pa1 = __hadd2(*(__half2*)&r0.y, *(__half2*)&r1.y);
        __half2 pb0 = __hadd2(*(__half2*)&r2.x, *(__half2*)&r3.x);
        __half2 pb1 = __hadd2(*(__half2*)&r2.y, *(__half2*)&r3.y);
        __half2 pc0 = __hadd2(*(__half2*)&r4.x, *(__half2*)&r5.x);
        __half2 pc1 = __hadd2(*(__half2*)&r4.y, *(__half2*)&r5.y);
        __half2 pd0 = __hadd2(*(__half2*)&r6.x, *(__half2*)&r7.x);
        __half2 pd1 = __hadd2(*(__half2*)&r6.y, *(__half2*)&r7.y);
        float2 fa0 = __half22float2(pa0), fa1 = __half22float2(pa1);
        float2 fb0 = __half22float2(pb0), fb1 = __half22float2(pb1);
        float2 fc0 = __half22float2(pc0), fc1 = __half22float2(pc1);
        float2 fd0 = __half22float2(pd0), fd1 = __half22float2(pd1);
        es.x += (fa0.x + fb0.x) + (fc0.x + fd0.x);
        es.y += (fa0.y + fb0.y) + (fc0.y + fd0.y);
        es.z += (fa1.x + fb1.x) + (fc1.x + fd1.x);
        es.w += (fa1.y + fb1.y) + (fc1.y + fd1.y);
    }
    if (j + 3 < nedge) {
        int4 q0 = ab4[j >> 2];
        uint2 r0 = *(const uint2*)(H + (size_t)q0.x * 128 + c0);
        uint2 r1 = *(const uint2*)(H + (size_t)q0.y * 128 + c0);
        uint2 r2 = *(const uint2*)(H + (size_t)q0.z * 128 + c0);
        uint2 r3 = *(const uint2*)(H + (size_t)q0.w * 128 + c0);
        __half2 pa0 = __hadd2(*(__half2*)&r0.x, *(__half2*)&r1.x);
        __half2 pa1 = __hadd2(*(__half2*)&r0.y, *(__half2*)&r1.y);
        __half2 pb0 = __hadd2(*(__half2*)&r2.x, *(__half2*)&r3.x);
        __half2 pb1 = __hadd2(*(__half2*)&r2.y, *(__half2*)&r3.y);
        float2 fa0 = __half22float2(pa0), fa1 = __half22float2(pa1);
        float2 fb0 = __half22float2(pb0), fb1 = __half22float2(pb1);
        es.x += fa0.x + fb0.x;
        es.y += fa0.y + fb0.y;
        es.z += fa1.x + fb1.x;
        es.w += fa1.y + fb1.y;
        j += 4;
    }
    const int* ab = adj + (size_t)row * MAXW;
    for (; j < nedge; j++) {
        float4 v = h4tof4(*(const uint2*)(H + (size_t)ab[j] * 128 + c0));
        es.x += v.x; es.y += v.y; es.z += v.z; es.w += v.w;
    }
    float4 bb = *(const float4*)(bias + c0);
    float ox = fmaxf(dinv_d * es.x + bb.x, 0.f);
    float oy = fmaxf(dinv_d * es.y + bb.y, 0.f);
    float oz = fmaxf(dinv_d * es.z + bb.z, 0.f);
    float ow = fmaxf(dinv_d * es.w + bb.w, 0.f);
    uint2 st;
    *(__half2*)&st.x = __floats2half2_rn(ox, oy);
    *(__half2*)&st.y = __floats2half2_rn(oz, ow);
    *(uint2*)(O + (size_t)row * 128 + c0) = st;
}

// ---------------------------------------------------------------------------
// agg64: half-warp per dst row (2 rows/warp); fp32 output + b2.
// ---------------------------------------------------------------------------
__global__ void k_agg64(const __half* __restrict__ H, const int* __restrict__ cnt,
                        const float* __restrict__ bias, const int* __restrict__ adj,
                        float* __restrict__ O, int N) {
    int lane = threadIdx.x & 31;
    int wid  = threadIdx.x >> 5;
    int half = lane >> 4;
    int sub  = lane & 15;
    int row  = blockIdx.x * 16 + wid * 2 + half;
    if (row >= N) return;
    int c0 = sub * 4;
    int deg_e = cnt[row];
    int nedge = deg_e < MAXW ? deg_e : MAXW;
    float dinv_d = rsqrtf((float)deg_e + 1.0f);

    const int4* ab4 = (const int4*)(adj + (size_t)row * MAXW);
    float4 es = h4tof4(*(const uint2*)(H + (size_t)row * 64 + c0));
    int j = 0;
    for (; j + 7 < nedge; j += 8) {
        int4 q0 = ab4[j >> 2];
        int4 q1 = ab4[(j >> 2) + 1];
        uint2 r0 = *(const uint2*)(H + (size_t)q0.x * 64 + c0);
        uint2 r1 = *(const uint2*)(H + (size_t)q0.y * 64 + c0);
        uint2 r2 = *(const uint2*)(H + (size_t)q0.z * 64 + c0);
        uint2 r3 = *(const uint2*)(H + (size_t)q0.w * 64 + c0);
        uint2 r4 = *(const uint2*)(H + (size_t)q1.x * 64 + c0);
        uint2 r5 = *(const uint2*)(H + (size_t)q1.y * 64 + c0);
        uint2 r6 = *(const uint2*)(H + (size_t)q1.z * 64 + c0);
        uint2 r7 = *(const uint2*)(H + (size_t)q1.w * 64 + c0);
        __half2 pa0 = __hadd2(*(__half2*)&r0.x, *(__half2*)&r1.x);
        __half2 pa1 = __hadd2(*(__half2*)&r0.y, *(__half2*)&r1.y);
        __half2 pb0 = __hadd2(*(__half2*)&r2.x, *(__half2*)&r3.x);
        __half2 pb1 = __hadd2(*(__half2*)&r2.y, *(__half2*)&r3.y);
        __half2 pc0 = __hadd2(*(__half2*)&r4.x, *(__half2*)&r5.x);
        __half2 pc1 = __hadd2(*(__half2*)&r4.y, *(__half2*)&r5.y);
        __half2 pd0 = __hadd2(*(__half2*)&r6.x, *(__half2*)&r7.x);
        __half2 pd1 = __hadd2(*(__half2*)&r6.y, *(__half2*)&r7.y);
        float2 fa0 = __half22float2(pa0), fa1 = __half22float2(pa1);
        float2 fb0 = __half22float2(pb0), fb1 = __half22float2(pb1);
        float2 fc0 = __half22float2(pc0), fc1 = __half22float2(pc1);
        float2 fd0 = __half22float2(pd0), fd1 = __half22float2(pd1);
        es.x += (fa0.x + fb0.x) + (fc0.x + fd0.x);
        es.y += (fa0.y + fb0.y) + (fc0.y + fd0.y);
        es.z += (fa1.x + fb1.x) + (fc1.x + fd1.x);
        es.w += (fa1.y + fb1.y) + (fc1.y + fd1.y);
    }
    if (j + 3 < nedge) {
        int4 q0 = ab4[j >> 2];
        uint2 r0 = *(const uint2*)(H + (size_t)q0.x * 64 + c0);
        uint2 r1 = *(const uint2*)(H + (size_t)q0.y * 64 + c0);
        uint2 r2 = *(const uint2*)(H + (size_t)q0.z * 64 + c0);
        uint2 r3 = *(const uint2*)(H + (size_t)q0.w * 64 + c0);
        __half2 pa0 = __hadd2(*(__half2*)&r0.x, *(__half2*)&r1.x);
        __half2 pa1 = __hadd2(*(__half2*)&r0.y, *(__half2*)&r1.y);
        __half2 pb0 = __hadd2(*(__half2*)&r2.x, *(__half2*)&r3.x);
        __half2 pb1 = __hadd2(*(__half2*)&r2.y, *(__half2*)&r3.y);
        float2 fa0 = __half22float2(pa0), fa1 = __half22float2(pa1);
        float2 fb0 = __half22float2(pb0), fb1 = __half22float2(pb1);
        es.x += fa0.x + fb0.x;
        es.y += fa0.y + fb0.y;
        es.z += fa1.x + fb1.x;
        es.w += fa1.y + fb1.y;
        j += 4;
    }
    const int* ab = adj + (size_t)row * MAXW;
    for (; j < nedge; j++) {
        float4 v = h4tof4(*(const uint2*)(H + (size_t)ab[j] * 64 + c0));
        es.x += v.x; es.y += v.y; es.z += v.z; es.w += v.w;
    }
    float4 bb = *(const float4*)(bias + c0);
    float4 o;
    o.x = dinv_d * es.x + bb.x;
    o.y = dinv_d * es.y + bb.y;
    o.z = dinv_d * es.z + bb.z;
    o.w = dinv_d * es.w + bb.w;
    *(float4*)(O + (size_t)row * 64 + c0) = o;
}

// ---------------------------------------------------------------------------
// Launch (single stream: memset + 5 kernels)
// ---------------------------------------------------------------------------
extern "C" void kernel_launch(void* const* d_in, const int* in_sizes, int n_in,
                              void* d_out, int out_size) {
    const float* x   = (const float*)d_in[0];
    const int*   ei  = (const int*)d_in[1];   // JAX int64 silently downcast to int32
    const float* W1  = (const float*)d_in[2];
    const float* b1  = (const float*)d_in[3];
    const float* W2  = (const float*)d_in[4];
    const float* b2  = (const float*)d_in[5];
    float*       out = (float*)d_out;

    int N = in_sizes[0] / 128;
    int E = in_sizes[1] / 2;

    __half *h1, *o1, *h2;
    int *cnt, *adj;
    cudaGetSymbolAddress((void**)&cnt, g_cnt);
    cudaGetSymbolAddress((void**)&adj, g_adj);
    cudaGetSymbolAddress((void**)&h1,  g_h1);
    cudaGetSymbolAddress((void**)&o1,  g_o1);
    cudaGetSymbolAddress((void**)&h2,  g_h2);

    const int BT = 256;
    int gE = (E + BT - 1) / BT;

    const int smem1 = (64 * 136 + 128 * 136) * (int)sizeof(__half);  // 52224 B
    const int smem2 = (64 * 136 + 64 * 136)  * (int)sizeof(__half);  // 34816 B
    cudaFuncSetAttribute(k_mma1, cudaFuncAttributeMaxDynamicSharedMemorySize, smem1);
    cudaFuncSetAttribute(k_mma2, cudaFuncAttributeMaxDynamicSharedMemorySize, smem2);

    int gRow = (N + 63) / 64;
    int gAgg128 = (N + 7) / 8;       // warp per row
    int gAgg64  = (N + 15) / 16;     // half-warp per row

    cudaMemsetAsync(cnt, 0, (size_t)N * sizeof(int), 0);
    k_fill<<<gE, BT>>>(ei, cnt, adj, E);

    // --- layer 1 ---
    k_mma1<<<gRow, BT, smem1>>>(x, W1, cnt, h1, N);
    k_agg128<<<gAgg128, BT>>>(h1, cnt, b1, adj, o1, N);

    // --- layer 2 ---
    k_mma2<<<gRow, BT, smem2>>>(o1, W2, cnt, h2, N);
    k_agg64<<<gAgg64, BT>>>(h2, cnt, b2, adj, out, N);
}

// round 17
// speedup vs baseline: 1.3012x; 1.3012x over previous
#include <cuda_runtime.h>
#include <cuda_fp16.h>
#include <cstdint>

#define MAXN 50048
#define MAXW 64                                // ELL width (deg ~ Poisson(16))

// ---------------- scratch (__device__ globals; no allocs allowed) ----------
__device__ int    g_cnt[MAXN];                 // in-degree counter / final degree
__device__ int    g_adj[(size_t)MAXN * MAXW];  // ELL adjacency: src ids (row 256B-aligned)
__device__ __half g_h1[(size_t)MAXN * 128];    // dinv * (X @ W1)       (fp16, pre-scaled)
__device__ __half g_o1[(size_t)MAXN * 128];    // relu(layer-1 out)     (fp16)
__device__ __half g_h2[(size_t)MAXN * 64];     // dinv * (relu(o1)@W2)  (fp16, pre-scaled)

__device__ __forceinline__ float4 h4tof4(uint2 raw) {
    float2 a = __half22float2(*(__half2*)&raw.x);
    float2 b = __half22float2(*(__half2*)&raw.y);
    return make_float4(a.x, a.y, b.x, b.y);
}

// ---------------------------------------------------------------------------
// fill: single pass builds ELL adjacency AND degree counts
// ---------------------------------------------------------------------------
__global__ void k_fill(const int* __restrict__ ei, int* __restrict__ cnt,
                       int* __restrict__ adj, int E) {
    int e = blockIdx.x * blockDim.x + threadIdx.x;
    if (e >= E) return;
    int src = ei[e];
    int dst = ei[E + e];
    int pos = atomicAdd(&cnt[dst], 1);
    if (pos < MAXW) adj[(size_t)dst * MAXW + pos] = src;
}

// ---------------------------------------------------------------------------
// mma body (R15-proven): tf32 mma.sync, fragments from fp16 smem (exact cvt;
// fp16 mantissa == tf32 mantissa). Xs stride 136, Ws stride C+8: conflict-free.
// ---------------------------------------------------------------------------
template <int C>
__device__ __forceinline__ void mma_body_epilogue(
    const __half* Xs, const __half* Ws, const int* __restrict__ cnt,
    __half* __restrict__ H, int N, int row0, int wid, int lane) {
    constexpr int K = 128;
    constexpr int XSS_H = 136, WSS_H = C + 8;
    constexpr int NTILES = C / 16;

    int m0 = (wid & 3) * 16;
    int nbase = (wid >> 2) * (C / 2);
    int r = lane >> 2;
    int c = lane & 3;

    float acc[NTILES][4];
#pragma unroll
    for (int t = 0; t < NTILES; t++) {
        acc[t][0] = 0.f; acc[t][1] = 0.f; acc[t][2] = 0.f; acc[t][3] = 0.f;
    }
#pragma unroll 4
    for (int k0 = 0; k0 < K; k0 += 8) {
        uint32_t a0 = __float_as_uint(__half2float(Xs[(m0 + r) * XSS_H + k0 + c]));
        uint32_t a1 = __float_as_uint(__half2float(Xs[(m0 + r + 8) * XSS_H + k0 + c]));
        uint32_t a2 = __float_as_uint(__half2float(Xs[(m0 + r) * XSS_H + k0 + c + 4]));
        uint32_t a3 = __float_as_uint(__half2float(Xs[(m0 + r + 8) * XSS_H + k0 + c + 4]));
#pragma unroll
        for (int t = 0; t < NTILES; t++) {
            int n0 = nbase + t * 8;
            uint32_t b0 = __float_as_uint(__half2float(Ws[(k0 + c) * WSS_H + n0 + r]));
            uint32_t b1 = __float_as_uint(__half2float(Ws[(k0 + c + 4) * WSS_H + n0 + r]));
            asm volatile(
                "mma.sync.aligned.m16n8k8.row.col.f32.tf32.tf32.f32 "
                "{%0,%1,%2,%3}, {%4,%5,%6,%7}, {%8,%9}, {%0,%1,%2,%3};"
                : "+f"(acc[t][0]), "+f"(acc[t][1]), "+f"(acc[t][2]), "+f"(acc[t][3])
                : "r"(a0), "r"(a1), "r"(a2), "r"(a3), "r"(b0), "r"(b1));
        }
    }

    int gr0 = row0 + m0 + r;
    int gr1 = gr0 + 8;
    float d0 = (gr0 < N) ? rsqrtf((float)cnt[gr0] + 1.0f) : 0.f;
    float d1 = (gr1 < N) ? rsqrtf((float)cnt[gr1] + 1.0f) : 0.f;
#pragma unroll
    for (int t = 0; t < NTILES; t++) {
        int col = nbase + t * 8 + 2 * c;
        if (gr0 < N)
            *(__half2*)(H + (size_t)gr0 * C + col) =
                __floats2half2_rn(d0 * acc[t][0], d0 * acc[t][1]);
        if (gr1 < N)
            *(__half2*)(H + (size_t)gr1 * C + col) =
                __floats2half2_rn(d1 * acc[t][2], d1 * acc[t][3]);
    }
}

// ---------------------------------------------------------------------------
// mma1: X(fp32) @ W1[128,128] -> prescaled fp16 h1.
// Two 64-row tiles per CTA; W staged once.
// ---------------------------------------------------------------------------
__global__ void k_mma1(const float* __restrict__ X, const float* __restrict__ W,
                       const int* __restrict__ cnt, __half* __restrict__ H, int N) {
    constexpr int C = 128, K = 128, BM = 64;
    constexpr int XSS_H = 136, WSS_H = C + 8;
    extern __shared__ __half smh[];
    __half* Xs = smh;                       // BM * XSS_H
    __half* Ws = smh + BM * XSS_H;          // K * WSS_H

    int tid = threadIdx.x;
    int wid = tid >> 5, lane = tid & 31;

    // stage W once
#pragma unroll
    for (int it = 0; it < (K * C) / (256 * 4); it++) {
        int i4 = tid + it * 256;
        int k = (i4 * 4) / C;
        int n = (i4 * 4) % C;
        float4 v = *(const float4*)(W + (size_t)k * C + n);
        uint2 st;
        *(__half2*)&st.x = __floats2half2_rn(v.x, v.y);
        *(__half2*)&st.y = __floats2half2_rn(v.z, v.w);
        *(uint2*)(Ws + k * WSS_H + n) = st;
    }

#pragma unroll
    for (int tile = 0; tile < 2; tile++) {
        int row0 = blockIdx.x * 128 + tile * BM;
        if (row0 >= N) break;
#pragma unroll
        for (int it = 0; it < (BM * K) / (256 * 4); it++) {
            int i4 = tid + it * 256;
            int m = i4 >> 5;
            int k = (i4 << 2) & 127;
            int gr = row0 + m;
            if (gr >= N) gr = N - 1;
            float4 v = *(const float4*)(X + (size_t)gr * K + k);
            uint2 st;
            *(__half2*)&st.x = __floats2half2_rn(v.x, v.y);
            *(__half2*)&st.y = __floats2half2_rn(v.z, v.w);
            *(uint2*)(Xs + m * XSS_H + k) = st;
        }
        __syncthreads();
        mma_body_epilogue<C>(Xs, Ws, cnt, H, N, row0, wid, lane);
        __syncthreads();
    }
}

// ---------------------------------------------------------------------------
// mma2: o1(fp16, relu'd) @ W2[128,64] -> prescaled fp16 h2.
// Two 64-row tiles per CTA; W staged once.
// ---------------------------------------------------------------------------
__global__ void k_mma2(const __half* __restrict__ X, const float* __restrict__ W,
                       const int* __restrict__ cnt, __half* __restrict__ H, int N) {
    constexpr int C = 64, K = 128, BM = 64;
    constexpr int XSS_H = 136, WSS_H = C + 8;
    extern __shared__ __half smh[];
    __half* Xs = smh;
    __half* Ws = smh + BM * XSS_H;

    int tid = threadIdx.x;
    int wid = tid >> 5, lane = tid & 31;

#pragma unroll
    for (int it = 0; it < (K * C) / (256 * 4); it++) {
        int i4 = tid + it * 256;
        int k = (i4 * 4) / C;
        int n = (i4 * 4) % C;
        float4 v = *(const float4*)(W + (size_t)k * C + n);
        uint2 st;
        *(__half2*)&st.x = __floats2half2_rn(v.x, v.y);
        *(__half2*)&st.y = __floats2half2_rn(v.z, v.w);
        *(uint2*)(Ws + k * WSS_H + n) = st;
    }

#pragma unroll
    for (int tile = 0; tile < 2; tile++) {
        int row0 = blockIdx.x * 128 + tile * BM;
        if (row0 >= N) break;
#pragma unroll
        for (int it = 0; it < (BM * K) / (256 * 4); it++) {
            int i4 = tid + it * 256;
            int m = i4 >> 5;
            int k = (i4 << 2) & 127;
            int gr = row0 + m;
            if (gr >= N) gr = N - 1;
            uint2 hv = *(const uint2*)(X + (size_t)gr * K + k);   // already fp16
            *(uint2*)(Xs + m * XSS_H + k) = hv;
        }
        __syncthreads();
        mma_body_epilogue<C>(Xs, Ws, cnt, H, N, row0, wid, lane);
        __syncthreads();
    }
}

// ---------------------------------------------------------------------------
// agg128: warp per dst row; fp16 output with fused relu.
// o1[row] = relu(dinv_d * (Sum hs[s] + hs[row]) + bias)   (fp16)
// ---------------------------------------------------------------------------
__global__ void k_agg128(const __half* __restrict__ H, const int* __restrict__ cnt,
                         const float* __restrict__ bias, const int* __restrict__ adj,
                         __half* __restrict__ O, int N) {
    int row  = blockIdx.x * (blockDim.x >> 5) + (threadIdx.x >> 5);
    int lane = threadIdx.x & 31;
    if (row >= N) return;
    int c0 = lane * 4;
    int deg_e = cnt[row];
    int nedge = deg_e < MAXW ? deg_e : MAXW;
    float dinv_d = rsqrtf((float)deg_e + 1.0f);

    const int4* ab4 = (const int4*)(adj + (size_t)row * MAXW);
    float4 es = h4tof4(*(const uint2*)(H + (size_t)row * 128 + c0));
    int j = 0;
    for (; j + 7 < nedge; j += 8) {
        int4 q0 = ab4[j >> 2];
        int4 q1 = ab4[(j >> 2) + 1];
        uint2 r0 = *(const uint2*)(H + (size_t)q0.x * 128 + c0);
        uint2 r1 = *(const uint2*)(H + (size_t)q0.y * 128 + c0);
        uint2 r2 = *(const uint2*)(H + (size_t)q0.z * 128 + c0);
        uint2 r3 = *(const uint2*)(H + (size_t)q0.w * 128 + c0);
        uint2 r4 = *(const uint2*)(H + (size_t)q1.x * 128 + c0);
        uint2 r5 = *(const uint2*)(H + (size_t)q1.y * 128 + c0);
        uint2 r6 = *(const uint2*)(H + (size_t)q1.z * 128 + c0);
        uint2 r7 = *(const uint2*)(H + (size_t)q1.w * 128 + c0);
        __half2 pa0 = __hadd2(*(__half2*)&r0.x, *(__half2*)&r1.x);
        __half2 pa1 = __hadd2(*(__half2*)&r0.y, *(__half2*)&r1.y);
        __half2 pb0 = __hadd2(*(__half2*)&r2.x, *(__half2*)&r3.x);
        __half2 pb1 = __hadd2(*(__half2*)&r2.y, *(__half2*)&r3.y);
        __half2 pc0 = __hadd2(*(__half2*)&r4.x, *(__half2*)&r5.x);
        __half2 pc1 = __hadd2(*(__half2*)&r4.y, *(__half2*)&r5.y);
        __half2 pd0 = __hadd2(*(__half2*)&r6.x, *(__half2*)&r7.x);
        __half2 pd1 = __hadd2(*(__half2*)&r6.y, *(__half2*)&r7.y);
        float2 fa0 = __half22float2(pa0), fa1 = __half22float2(pa1);
        float2 fb0 = __half22float2(pb0), fb1 = __half22float2(pb1);
        float2 fc0 = __half22float2(pc0), fc1 = __half22float2(pc1);
        float2 fd0 = __half22float2(pd0), fd1 = __half22float2(pd1);
        es.x += (fa0.x + fb0.x) + (fc0.x + fd0.x);
        es.y += (fa0.y + fb0.y) + (fc0.y + fd0.y);
        es.z += (fa1.x + fb1.x) + (fc1.x + fd1.x);
        es.w += (fa1.y + fb1.y) + (fc1.y + fd1.y);
    }
    if (j + 3 < nedge) {
        int4 q0 = ab4[j >> 2];
        uint2 r0 = *(const uint2*)(H + (size_t)q0.x * 128 + c0);
        uint2 r1 = *(const uint2*)(H + (size_t)q0.y * 128 + c0);
        uint2 r2 = *(const uint2*)(H + (size_t)q0.z * 128 + c0);
        uint2 r3 = *(const uint2*)(H + (size_t)q0.w * 128 + c0);
        __half2 pa0 = __hadd2(*(__half2*)&r0.x, *(__half2*)&r1.x);
        __half2 pa1 = __hadd2(*(__half2*)&r0.y, *(__half2*)&r1.y);
        __half2 pb0 = __hadd2(*(__half2*)&r2.x, *(__half2*)&r3.x);
        __half2 pb1 = __hadd2(*(__half2*)&r2.y, *(__half2*)&r3.y);
        float2 fa0 = __half22float2(pa0), fa1 = __half22float2(pa1);
        float2 fb0 = __half22float2(pb0), fb1 = __half22float2(pb1);
        es.x += fa0.x + fb0.x;
        es.y += fa0.y + fb0.y;
        es.z += fa1.x + fb1.x;
        es.w += fa1.y + fb1.y;
        j += 4;
    }
    const int* ab = adj + (size_t)row * MAXW;
    for (; j < nedge; j++) {
        float4 v = h4tof4(*(const uint2*)(H + (size_t)ab[j] * 128 + c0));
        es.x += v.x; es.y += v.y; es.z += v.z; es.w += v.w;
    }
    float4 bb = *(const float4*)(bias + c0);
    float ox = fmaxf(dinv_d * es.x + bb.x, 0.f);
    float oy = fmaxf(dinv_d * es.y + bb.y, 0.f);
    float oz = fmaxf(dinv_d * es.z + bb.z, 0.f);
    float ow = fmaxf(dinv_d * es.w + bb.w, 0.f);
    uint2 st;
    *(__half2*)&st.x = __floats2half2_rn(ox, oy);
    *(__half2*)&st.y = __floats2half2_rn(oz, ow);
    *(uint2*)(O + (size_t)row * 128 + c0) = st;
}

// ---------------------------------------------------------------------------
// agg64: half-warp per dst row (2 rows/warp); fp32 output + b2.
// ---------------------------------------------------------------------------
__global__ void k_agg64(const __half* __restrict__ H, const int* __restrict__ cnt,
                        const float* __restrict__ bias, const int* __restrict__ adj,
                        float* __restrict__ O, int N) {
    int lane = threadIdx.x & 31;
    int wid  = threadIdx.x >> 5;
    int half = lane >> 4;
    int sub  = lane & 15;
    int row  = blockIdx.x * 16 + wid * 2 + half;
    if (row >= N) return;
    int c0 = sub * 4;
    int deg_e = cnt[row];
    int nedge = deg_e < MAXW ? deg_e : MAXW;
    float dinv_d = rsqrtf((float)deg_e + 1.0f);

    const int4* ab4 = (const int4*)(adj + (size_t)row * MAXW);
    float4 es = h4tof4(*(const uint2*)(H + (size_t)row * 64 + c0));
    int j = 0;
    for (; j + 7 < nedge; j += 8) {
        int4 q0 = ab4[j >> 2];
        int4 q1 = ab4[(j >> 2) + 1];
        uint2 r0 = *(const uint2*)(H + (size_t)q0.x * 64 + c0);
        uint2 r1 = *(const uint2*)(H + (size_t)q0.y * 64 + c0);
        uint2 r2 = *(const uint2*)(H + (size_t)q0.z * 64 + c0);
        uint2 r3 = *(const uint2*)(H + (size_t)q0.w * 64 + c0);
        uint2 r4 = *(const uint2*)(H + (size_t)q1.x * 64 + c0);
        uint2 r5 = *(const uint2*)(H + (size_t)q1.y * 64 + c0);
        uint2 r6 = *(const uint2*)(H + (size_t)q1.z * 64 + c0);
        uint2 r7 = *(const uint2*)(H + (size_t)q1.w * 64 + c0);
        __half2 pa0 = __hadd2(*(__half2*)&r0.x, *(__half2*)&r1.x);
        __half2 pa1 = __hadd2(*(__half2*)&r0.y, *(__half2*)&r1.y);
        __half2 pb0 = __hadd2(*(__half2*)&r2.x, *(__half2*)&r3.x);
        __half2 pb1 = __hadd2(*(__half2*)&r2.y, *(__half2*)&r3.y);
        __half2 pc0 = __hadd2(*(__half2*)&r4.x, *(__half2*)&r5.x);
        __half2 pc1 = __hadd2(*(__half2*)&r4.y, *(__half2*)&r5.y);
        __half2 pd0 = __hadd2(*(__half2*)&r6.x, *(__half2*)&r7.x);
        __half2 pd1 = __hadd2(*(__half2*)&r6.y, *(__half2*)&r7.y);
        float2 fa0 = __half22float2(pa0), fa1 = __half22float2(pa1);
        float2 fb0 = __half22float2(pb0), fb1 = __half22float2(pb1);
        float2 fc0 = __half22float2(pc0), fc1 = __half22float2(pc1);
        float2 fd0 = __half22float2(pd0), fd1 = __half22float2(pd1);
        es.x += (fa0.x + fb0.x) + (fc0.x + fd0.x);
        es.y += (fa0.y + fb0.y) + (fc0.y + fd0.y);
        es.z += (fa1.x + fb1.x) + (fc1.x + fd1.x);
        es.w += (fa1.y + fb1.y) + (fc1.y + fd1.y);
    }
    if (j + 3 < nedge) {
        int4 q0 = ab4[j >> 2];
        uint2 r0 = *(const uint2*)(H + (size_t)q0.x * 64 + c0);
        uint2 r1 = *(const uint2*)(H + (size_t)q0.y * 64 + c0);
        uint2 r2 = *(const uint2*)(H + (size_t)q0.z * 64 + c0);
        uint2 r3 = *(const uint2*)(H + (size_t)q0.w * 64 + c0);
        __half2 pa0 = __hadd2(*(__half2*)&r0.x, *(__half2*)&r1.x);
        __half2 pa1 = __hadd2(*(__half2*)&r0.y, *(__half2*)&r1.y);
        __half2 pb0 = __hadd2(*(__half2*)&r2.x, *(__half2*)&r3.x);
        __half2 pb1 = __hadd2(*(__half2*)&r2.y, *(__half2*)&r3.y);
        float2 fa0 = __half22float2(pa0), fa1 = __half22float2(pa1);
        float2 fb0 = __half22float2(pb0), fb1 = __half22float2(pb1);
        es.x += fa0.x + fb0.x;
        es.y += fa0.y + fb0.y;
        es.z += fa1.x + fb1.x;
        es.w += fa1.y + fb1.y;
        j += 4;
    }
    const int* ab = adj + (size_t)row * MAXW;
    for (; j < nedge; j++) {
        float4 v = h4tof4(*(const uint2*)(H + (size_t)ab[j] * 64 + c0));
        es.x += v.x; es.y += v.y; es.z += v.z; es.w += v.w;
    }
    float4 bb = *(const float4*)(bias + c0);
    float4 o;
    o.x = dinv_d * es.x + bb.x;
    o.y = dinv_d * es.y + bb.y;
    o.z = dinv_d * es.z + bb.z;
    o.w = dinv_d * es.w + bb.w;
    *(float4*)(O + (size_t)row * 64 + c0) = o;
}

// ---------------------------------------------------------------------------
// Launch (single stream: memset + 5 kernels)
// ---------------------------------------------------------------------------
extern "C" void kernel_launch(void* const* d_in, const int* in_sizes, int n_in,
                              void* d_out, int out_size) {
    const float* x   = (const float*)d_in[0];
    const int*   ei  = (const int*)d_in[1];   // JAX int64 silently downcast to int32
    const float* W1  = (const float*)d_in[2];
    const float* b1  = (const float*)d_in[3];
    const float* W2  = (const float*)d_in[4];
    const float* b2  = (const float*)d_in[5];
    float*       out = (float*)d_out;

    int N = in_sizes[0] / 128;
    int E = in_sizes[1] / 2;

    __half *h1, *o1, *h2;
    int *cnt, *adj;
    cudaGetSymbolAddress((void**)&cnt, g_cnt);
    cudaGetSymbolAddress((void**)&adj, g_adj);
    cudaGetSymbolAddress((void**)&h1,  g_h1);
    cudaGetSymbolAddress((void**)&o1,  g_o1);
    cudaGetSymbolAddress((void**)&h2,  g_h2);

    const int BT = 256;
    int gE = (E + BT - 1) / BT;

    const int smem1 = (64 * 136 + 128 * 136) * (int)sizeof(__half);  // 52224 B
    const int smem2 = (64 * 136 + 128 * 72)  * (int)sizeof(__half);  // 35840 B
    cudaFuncSetAttribute(k_mma1, cudaFuncAttributeMaxDynamicSharedMemorySize, smem1);
    cudaFuncSetAttribute(k_mma2, cudaFuncAttributeMaxDynamicSharedMemorySize, smem2);

    int gRow2 = (N + 127) / 128;     // two 64-row tiles per CTA
    int gAgg128 = (N + 7) / 8;       // warp per row
    int gAgg64  = (N + 15) / 16;     // half-warp per row

    cudaMemsetAsync(cnt, 0, (size_t)N * sizeof(int), 0);
    k_fill<<<gE, BT>>>(ei, cnt, adj, E);

    // --- layer 1 ---
    k_mma1<<<gRow2, BT, smem1>>>(x, W1, cnt, h1, N);
    k_agg128<<<gAgg128, BT>>>(h1, cnt, b1, adj, o1, N);

    // --- layer 2 ---
    k_mma2<<<gRow2, BT, smem2>>>(o1, W2, cnt, h2, N);
    k_agg64<<<gAgg64, BT>>>(h2, cnt, b2, adj, out, N);
}